// round 1
// baseline (speedup 1.0000x reference)
#include <cuda_runtime.h>
#include <math.h>

#define L_SEQ  2048
#define BATCH  2
#define DM     1024
#define NH     16
#define DK     64
#define E3     3072            // 3 * DM
#define MROWS  (L_SEQ * BATCH) // 4096

// Scratch (module-load allocation, allowed)
__device__ float g_Q[NH * BATCH * L_SEQ * DK];
__device__ float g_K[NH * BATCH * L_SEQ * DK];
__device__ float g_V[NH * BATCH * L_SEQ * DK];

// ---------------------------------------------------------------------------
// Kernel 1: QKV projection  C[m, e] = sum_d X[m, d] * W[e, d]
// 128x128 block tile, BK=16, 8x8 per-thread microtile, 256 threads.
// Epilogue scatters directly into per-head Q/K/V layout [h][b][l][d].
// ---------------------------------------------------------------------------
__global__ __launch_bounds__(256) void qkv_gemm_kernel(
    const float* __restrict__ X, const float* __restrict__ W)
{
    const int BK = 16;
    __shared__ float As[16][132];   // As[k][m]  (transposed, padded)
    __shared__ float Bs[16][132];   // Bs[k][n]

    const int tid = threadIdx.x;
    const int m0  = blockIdx.y * 128;
    const int n0  = blockIdx.x * 128;
    const int tr  = tid >> 4;   // 0..15
    const int tc  = tid & 15;   // 0..15

    float acc[8][8];
#pragma unroll
    for (int i = 0; i < 8; i++)
#pragma unroll
        for (int j = 0; j < 8; j++) acc[i][j] = 0.f;

    for (int k0 = 0; k0 < DM; k0 += BK) {
#pragma unroll
        for (int it = 0; it < 2; it++) {
            int idx = tid + it * 256;     // 0..511 float4 slots
            int row = idx >> 2;           // 0..127
            int c4  = (idx & 3) * 4;      // 0,4,8,12
            float4 va = *(const float4*)(X + (size_t)(m0 + row) * DM + k0 + c4);
            As[c4 + 0][row] = va.x;
            As[c4 + 1][row] = va.y;
            As[c4 + 2][row] = va.z;
            As[c4 + 3][row] = va.w;
            float4 vb = *(const float4*)(W + (size_t)(n0 + row) * DM + k0 + c4);
            Bs[c4 + 0][row] = vb.x;
            Bs[c4 + 1][row] = vb.y;
            Bs[c4 + 2][row] = vb.z;
            Bs[c4 + 3][row] = vb.w;
        }
        __syncthreads();

#pragma unroll
        for (int k = 0; k < BK; k++) {
            float a[8], b[8];
            float4 a0 = *(const float4*)&As[k][tr * 8];
            float4 a1 = *(const float4*)&As[k][tr * 8 + 4];
            float4 b0 = *(const float4*)&Bs[k][tc * 8];
            float4 b1 = *(const float4*)&Bs[k][tc * 8 + 4];
            a[0]=a0.x; a[1]=a0.y; a[2]=a0.z; a[3]=a0.w;
            a[4]=a1.x; a[5]=a1.y; a[6]=a1.z; a[7]=a1.w;
            b[0]=b0.x; b[1]=b0.y; b[2]=b0.z; b[3]=b0.w;
            b[4]=b1.x; b[5]=b1.y; b[6]=b1.z; b[7]=b1.w;
#pragma unroll
            for (int i = 0; i < 8; i++)
#pragma unroll
                for (int j = 0; j < 8; j++)
                    acc[i][j] = fmaf(a[i], b[j], acc[i][j]);
        }
        __syncthreads();
    }

    // Epilogue scatter into g_Q / g_K / g_V with layout [(h*B + b)*L + l]*64 + d
#pragma unroll
    for (int i = 0; i < 8; i++) {
        int m = m0 + tr * 8 + i;
        int l = m / BATCH;
        int b = m % BATCH;
#pragma unroll
        for (int j = 0; j < 8; j++) {
            int n  = n0 + tc * 8 + j;
            int h  = n / (3 * DK);
            int jj = n % (3 * DK);
            int t  = jj / DK;
            int d  = jj % DK;
            float* dst = (t == 0) ? g_Q : (t == 1) ? g_K : g_V;
            dst[(((size_t)h * BATCH + b) * L_SEQ + l) * DK + d] = acc[i][j];
        }
    }
}

// ---------------------------------------------------------------------------
// Kernel 2: RoPE on first 32 dims of Q and K.
// One thread per (hb, l, j) with j in [0,16): rotates pair (j, j+16).
// ---------------------------------------------------------------------------
__global__ __launch_bounds__(256) void rope_kernel()
{
    int idx = blockIdx.x * 256 + threadIdx.x;   // < 32 * 2048 * 16
    int j  = idx & 15;
    int l  = (idx >> 4) & (L_SEQ - 1);
    int hb = idx >> 15;                          // < 32
    size_t base = ((size_t)hb * L_SEQ + l) * DK;

    float theta = powf(10000.0f, -(float)j * (1.0f / 16.0f));
    float arg = (float)l * theta;   // same fp32 rounding as the reference
    float sn, cs;
    sincosf(arg, &sn, &cs);

    float q1 = g_Q[base + j], q2 = g_Q[base + j + 16];
    g_Q[base + j]      = q1 * cs - q2 * sn;
    g_Q[base + j + 16] = q2 * cs + q1 * sn;

    float k1 = g_K[base + j], k2 = g_K[base + j + 16];
    g_K[base + j]      = k1 * cs - k2 * sn;
    g_K[base + j + 16] = k2 * cs + k1 * sn;
}

// ---------------------------------------------------------------------------
// Kernel 3: flash-style attention. One block = one (h,b) pair x 64 query rows.
// 256 threads as 16x16; each thread owns a 4x4 microtile of S and of O.
// Online softmax (running max + sum), K processed in 64-row chunks.
// ---------------------------------------------------------------------------
#define SSTR 68   // padded smem row stride (floats)
#define ATT_SMEM_BYTES (4 * 64 * SSTR * 4)   // Qt, Kt, Vs, Ps = 69632 B

__global__ __launch_bounds__(256) void attn_kernel(float* __restrict__ out)
{
    extern __shared__ float sm[];
    float* Qt = sm;                 // Qt[d][r]
    float* Kt = sm + 64 * SSTR;     // Kt[d][c]
    float* Vs = sm + 2 * 64 * SSTR; // Vs[c][d]
    float* Ps = sm + 3 * 64 * SSTR; // Ps[r][c]

    const int tid = threadIdx.x;
    const int ty  = tid >> 4;
    const int tx  = tid & 15;
    const int r0  = ty * 4;
    const int c0  = tx * 4;

    const int q0 = blockIdx.x * 64;
    const int hb = blockIdx.y;           // h*B + b
    const int h  = hb >> 1;
    const int b  = hb & 1;

    const float* Qg = g_Q + (size_t)hb * L_SEQ * DK;
    const float* Kg = g_K + (size_t)hb * L_SEQ * DK;
    const float* Vg = g_V + (size_t)hb * L_SEQ * DK;

    // Load Q tile transposed: Qt[d][r]
#pragma unroll
    for (int it = 0; it < 4; it++) {
        int idx = tid + it * 256;        // 0..1023 float4 slots
        int row = idx >> 4;              // 0..63
        int d4  = (idx & 15) * 4;
        float4 v = *(const float4*)(Qg + (size_t)(q0 + row) * DK + d4);
        Qt[(d4 + 0) * SSTR + row] = v.x;
        Qt[(d4 + 1) * SSTR + row] = v.y;
        Qt[(d4 + 2) * SSTR + row] = v.z;
        Qt[(d4 + 3) * SSTR + row] = v.w;
    }

    float o[4][4];
    float mrow[4], lrow[4];
#pragma unroll
    for (int i = 0; i < 4; i++) {
        mrow[i] = -1e30f;
        lrow[i] = 0.f;
#pragma unroll
        for (int j = 0; j < 4; j++) o[i][j] = 0.f;
    }

    for (int kc = 0; kc < L_SEQ; kc += 64) {
        __syncthreads();   // prior PV / Ps reads complete before overwrite
        // Load K (transposed) and V chunk
#pragma unroll
        for (int it = 0; it < 4; it++) {
            int idx = tid + it * 256;
            int row = idx >> 4;
            int d4  = (idx & 15) * 4;
            float4 vk = *(const float4*)(Kg + (size_t)(kc + row) * DK + d4);
            Kt[(d4 + 0) * SSTR + row] = vk.x;
            Kt[(d4 + 1) * SSTR + row] = vk.y;
            Kt[(d4 + 2) * SSTR + row] = vk.z;
            Kt[(d4 + 3) * SSTR + row] = vk.w;
            float4 vv = *(const float4*)(Vg + (size_t)(kc + row) * DK + d4);
            *(float4*)&Vs[row * SSTR + d4] = vv;
        }
        __syncthreads();

        // S = Q K^T (4x4 microtile)
        float s[4][4];
#pragma unroll
        for (int i = 0; i < 4; i++)
#pragma unroll
            for (int j = 0; j < 4; j++) s[i][j] = 0.f;

#pragma unroll 4
        for (int d = 0; d < 64; d++) {
            float4 av = *(const float4*)(Qt + d * SSTR + r0);
            float4 bv = *(const float4*)(Kt + d * SSTR + c0);
            float a[4] = {av.x, av.y, av.z, av.w};
            float bb[4] = {bv.x, bv.y, bv.z, bv.w};
#pragma unroll
            for (int i = 0; i < 4; i++)
#pragma unroll
                for (int j = 0; j < 4; j++)
                    s[i][j] = fmaf(a[i], bb[j], s[i][j]);
        }

        // Online softmax update
        const float scale = 0.125f;   // 1/sqrt(64)
        float alpha[4];
#pragma unroll
        for (int i = 0; i < 4; i++) {
            float mx = s[i][0] * scale;
#pragma unroll
            for (int j = 0; j < 4; j++) {
                s[i][j] *= scale;
                mx = fmaxf(mx, s[i][j]);
            }
            mx = fmaxf(mx, __shfl_xor_sync(0xffffffffu, mx, 8, 16));
            mx = fmaxf(mx, __shfl_xor_sync(0xffffffffu, mx, 4, 16));
            mx = fmaxf(mx, __shfl_xor_sync(0xffffffffu, mx, 2, 16));
            mx = fmaxf(mx, __shfl_xor_sync(0xffffffffu, mx, 1, 16));

            float mnew = fmaxf(mrow[i], mx);
            float a_   = __expf(mrow[i] - mnew);
            alpha[i]   = a_;
            mrow[i]    = mnew;

            float rs = 0.f;
#pragma unroll
            for (int j = 0; j < 4; j++) {
                s[i][j] = __expf(s[i][j] - mnew);
                rs += s[i][j];
            }
            rs += __shfl_xor_sync(0xffffffffu, rs, 8, 16);
            rs += __shfl_xor_sync(0xffffffffu, rs, 4, 16);
            rs += __shfl_xor_sync(0xffffffffu, rs, 2, 16);
            rs += __shfl_xor_sync(0xffffffffu, rs, 1, 16);
            lrow[i] = lrow[i] * a_ + rs;
        }

        // Write P tile
#pragma unroll
        for (int i = 0; i < 4; i++) {
            float4 pv = make_float4(s[i][0], s[i][1], s[i][2], s[i][3]);
            *(float4*)&Ps[(r0 + i) * SSTR + c0] = pv;
        }
        __syncthreads();

        // O = alpha*O + P @ V
#pragma unroll
        for (int i = 0; i < 4; i++)
#pragma unroll
            for (int j = 0; j < 4; j++) o[i][j] *= alpha[i];

#pragma unroll 2
        for (int c = 0; c < 64; c += 4) {
            float p[4][4], v[4][4];
#pragma unroll
            for (int i = 0; i < 4; i++) {
                float4 pv = *(const float4*)(Ps + (r0 + i) * SSTR + c);
                p[i][0] = pv.x; p[i][1] = pv.y; p[i][2] = pv.z; p[i][3] = pv.w;
            }
#pragma unroll
            for (int u = 0; u < 4; u++) {
                float4 vv = *(const float4*)(Vs + (c + u) * SSTR + c0);
                v[u][0] = vv.x; v[u][1] = vv.y; v[u][2] = vv.z; v[u][3] = vv.w;
            }
#pragma unroll
            for (int i = 0; i < 4; i++)
#pragma unroll
                for (int u = 0; u < 4; u++)
#pragma unroll
                    for (int j = 0; j < 4; j++)
                        o[i][j] = fmaf(p[i][u], v[u][j], o[i][j]);
        }
    }

    // Normalize and write output: out[l][b][h*64 + d]
#pragma unroll
    for (int i = 0; i < 4; i++) {
        float inv = 1.0f / lrow[i];
        int l = q0 + r0 + i;
        float4 ov = make_float4(o[i][0] * inv, o[i][1] * inv,
                                o[i][2] * inv, o[i][3] * inv);
        *(float4*)(out + ((size_t)l * BATCH + b) * DM + h * DK + c0) = ov;
    }
}

// ---------------------------------------------------------------------------
extern "C" void kernel_launch(void* const* d_in, const int* in_sizes, int n_in,
                              void* d_out, int out_size)
{
    const float* X = (const float*)d_in[0];        // (L, B, 1024)
    const float* W = (const float*)d_in[1];        // (3072, 1024)
    float* out = (float*)d_out;                    // (L, B, 1024)

    dim3 g1(E3 / 128, MROWS / 128);                // (24, 32)
    qkv_gemm_kernel<<<g1, 256>>>(X, W);

    rope_kernel<<<(NH * BATCH * L_SEQ * 16) / 256, 256>>>();

    cudaFuncSetAttribute(attn_kernel,
                         cudaFuncAttributeMaxDynamicSharedMemorySize,
                         ATT_SMEM_BYTES);
    attn_kernel<<<dim3(L_SEQ / 64, NH * BATCH), 256, ATT_SMEM_BYTES>>>(out);
}

// round 3
// speedup vs baseline: 2.7849x; 2.7849x over previous
#include <cuda_runtime.h>
#include <cstdint>
#include <math.h>

#define L_SEQ  2048
#define BATCH  2
#define DM     1024
#define NH     16
#define DK     64
#define E3     3072
#define MROWS  (L_SEQ * BATCH)
#define HB     (NH * BATCH)     // 32

// Scratch (static device allocations — allowed)
__device__ float g_Q[HB * L_SEQ * DK];   // [hb][l][d]
__device__ float g_K[HB * L_SEQ * DK];   // [hb][l][d]
__device__ float g_V[HB * L_SEQ * DK];   // [hb][l][d]

// ---------------------------------------------------------------------------
// helpers
// ---------------------------------------------------------------------------
__device__ __forceinline__ uint32_t cvt_tf32(float x) {
    uint32_t u;
    asm("cvt.rna.tf32.f32 %0, %1;" : "=r"(u) : "f"(x));
    return u;
}

// D += A(16x8) * B(8x8), tf32 inputs, f32 accum
__device__ __forceinline__ void mma_tf32(float* d, const uint32_t* a, const uint32_t* b) {
    asm volatile(
        "mma.sync.aligned.m16n8k8.row.col.f32.tf32.tf32.f32 "
        "{%0,%1,%2,%3}, {%4,%5,%6,%7}, {%8,%9}, {%0,%1,%2,%3};"
        : "+f"(d[0]), "+f"(d[1]), "+f"(d[2]), "+f"(d[3])
        : "r"(a[0]), "r"(a[1]), "r"(a[2]), "r"(a[3]), "r"(b[0]), "r"(b[1]));
}

// fast exp on the FMA pipe; input effectively <= 0
__device__ __forceinline__ float fexp(float x) {
    x = fmaxf(x, -80.0f);
    float t = x * 1.4426950408889634f;
    float n = rintf(t);
    float r = fmaf(n, -0.6931471805599453f, x);
    float p = fmaf(r, 0.00833333333f, 0.04166666667f);
    p = fmaf(p, r, 0.16666666667f);
    p = fmaf(p, r, 0.5f);
    p = fmaf(p, r, 1.0f);
    p = fmaf(p, r, 1.0f);
    return p * __int_as_float(((int)n + 127) << 23);
}

// ---------------------------------------------------------------------------
// Kernel 1: QKV projection, tf32 mma.sync.
// C[m,n] = sum_k X[m,k] * W[n,k].  CTA tile 128x128, BK=32, 8 warps (2x4),
// warp tile 64x32 (4 mtiles x 4 ntiles of m16n8k8).
// Epilogue scatters into g_Q/g_K/g_V with layout [hb][l][d].
// ---------------------------------------------------------------------------
__global__ __launch_bounds__(256) void qkv_mma_kernel(
    const float* __restrict__ X, const float* __restrict__ W)
{
    __shared__ uint32_t As[128][36];   // [m][k] tf32, stride 36 (conflict-free)
    __shared__ uint32_t Bs[128][36];   // [n][k] tf32

    const int tid  = threadIdx.x;
    const int lane = tid & 31;
    const int w    = tid >> 5;
    const int wm   = w >> 2;       // 0..1
    const int wn   = w & 3;        // 0..3
    const int g    = lane >> 2;    // groupID 0..7
    const int j    = lane & 3;     // 0..3

    const int m0 = blockIdx.y * 128;
    const int n0 = blockIdx.x * 128;

    float acc[4][4][4];
#pragma unroll
    for (int mt = 0; mt < 4; mt++)
#pragma unroll
        for (int nt = 0; nt < 4; nt++)
#pragma unroll
            for (int e = 0; e < 4; e++) acc[mt][nt][e] = 0.f;

    for (int s = 0; s < 32; s++) {
        const int k0 = s * 32;
        float4 va[4], vb[4];
#pragma unroll
        for (int it = 0; it < 4; it++) {
            int idx = tid + it * 256;          // 0..1023 float4 slots
            int r   = idx >> 3;                // 0..127
            int c4  = (idx & 7) * 4;           // 0..28
            va[it] = *(const float4*)(X + (size_t)(m0 + r) * DM + k0 + c4);
            vb[it] = *(const float4*)(W + (size_t)(n0 + r) * DM + k0 + c4);
        }
        __syncthreads();
#pragma unroll
        for (int it = 0; it < 4; it++) {
            int idx = tid + it * 256;
            int r   = idx >> 3;
            int c4  = (idx & 7) * 4;
            As[r][c4 + 0] = cvt_tf32(va[it].x);
            As[r][c4 + 1] = cvt_tf32(va[it].y);
            As[r][c4 + 2] = cvt_tf32(va[it].z);
            As[r][c4 + 3] = cvt_tf32(va[it].w);
            Bs[r][c4 + 0] = cvt_tf32(vb[it].x);
            Bs[r][c4 + 1] = cvt_tf32(vb[it].y);
            Bs[r][c4 + 2] = cvt_tf32(vb[it].z);
            Bs[r][c4 + 3] = cvt_tf32(vb[it].w);
        }
        __syncthreads();

#pragma unroll
        for (int ks = 0; ks < 4; ks++) {
            const int kk = ks * 8;
            uint32_t af[4][4];
#pragma unroll
            for (int mt = 0; mt < 4; mt++) {
                int row = wm * 64 + mt * 16 + g;
                af[mt][0] = As[row][kk + j];
                af[mt][1] = As[row + 8][kk + j];
                af[mt][2] = As[row][kk + j + 4];
                af[mt][3] = As[row + 8][kk + j + 4];
            }
#pragma unroll
            for (int nt = 0; nt < 4; nt++) {
                int col = wn * 32 + nt * 8 + g;
                uint32_t bf[2] = { Bs[col][kk + j], Bs[col][kk + j + 4] };
#pragma unroll
                for (int mt = 0; mt < 4; mt++)
                    mma_tf32(acc[mt][nt], af[mt], bf);
            }
        }
    }

    // epilogue scatter
#pragma unroll
    for (int mt = 0; mt < 4; mt++) {
#pragma unroll
        for (int nt = 0; nt < 4; nt++) {
            int col = n0 + wn * 32 + nt * 8 + 2 * j;
            int h   = col / 192;
            int jj  = col - h * 192;
            int t   = jj >> 6;
            int d   = jj & 63;
#pragma unroll
            for (int rr = 0; rr < 2; rr++) {
                int row = m0 + wm * 64 + mt * 16 + g + rr * 8;
                int l = row >> 1, b = row & 1;
                int hb = h * 2 + b;
                float2 v = make_float2(acc[mt][nt][rr * 2], acc[mt][nt][rr * 2 + 1]);
                float* dst = (t == 0) ? g_Q : (t == 1) ? g_K : g_V;
                *(float2*)&dst[(((size_t)hb * L_SEQ) + l) * DK + d] = v;
            }
        }
    }
}

// ---------------------------------------------------------------------------
// Kernel 2: RoPE on first 32 dims of Q and K
// ---------------------------------------------------------------------------
__global__ __launch_bounds__(256) void rope_kernel()
{
    int idx = blockIdx.x * 256 + threadIdx.x;
    int j  = idx & 15;
    int l  = (idx >> 4) & (L_SEQ - 1);
    int hb = idx >> 15;
    size_t base = ((size_t)hb * L_SEQ + l) * DK;

    float theta = powf(10000.0f, -(float)j * (1.0f / 16.0f));
    float arg = (float)l * theta;
    float sn, cs;
    sincosf(arg, &sn, &cs);

    float q1 = g_Q[base + j], q2 = g_Q[base + j + 16];
    g_Q[base + j]      = q1 * cs - q2 * sn;
    g_Q[base + j + 16] = q2 * cs + q1 * sn;

    float k1 = g_K[base + j], k2 = g_K[base + j + 16];
    g_K[base + j]      = k1 * cs - k2 * sn;
    g_K[base + j + 16] = k2 * cs + k1 * sn;
}

// ---------------------------------------------------------------------------
// Kernel 3: fused flash attention, tf32 mma.sync.
// CTA: 128 q rows x one (h,b). 8 warps x 16 q-rows each.
// Q fragments live in registers for the whole kernel (scale folded in).
// Per 64-key chunk: S = QK^T (mma) -> online softmax (registers) ->
// P (tf32) into smem aliasing K tile -> O += P V (mma).
// ---------------------------------------------------------------------------
#define KS_STRIDE 68
#define VS_STRIDE 72
#define PS_BYTES  (128 * KS_STRIDE * 4)          // 34816 (K tile aliased inside)
#define FLASH_SMEM (PS_BYTES + 64 * VS_STRIDE * 4) // + 18432 = 53248

__global__ __launch_bounds__(256, 1) void flash_kernel(float* __restrict__ out)
{
    extern __shared__ char smraw[];
    uint32_t* KPs = (uint32_t*)smraw;                 // K tile (64xKS) / P tile (128xKS)
    uint32_t* Vsm = (uint32_t*)(smraw + PS_BYTES);    // V tile [key][d], stride 72

    const int tid  = threadIdx.x;
    const int lane = tid & 31;
    const int w    = tid >> 5;     // 0..7
    const int g    = lane >> 2;
    const int j    = lane & 3;

    const int q0 = blockIdx.x * 128;
    const int hb = blockIdx.y;
    const int h  = hb >> 1, b = hb & 1;

    const float* Qg = g_Q + (size_t)hb * L_SEQ * DK;
    const float* Kg = g_K + (size_t)hb * L_SEQ * DK;
    const float* Vg = g_V + (size_t)hb * L_SEQ * DK;

    // Q fragments (x 1/8 scale), kept for all chunks
    uint32_t qa[8][4];
    {
        int r0 = q0 + w * 16 + g;
#pragma unroll
        for (int ks = 0; ks < 8; ks++) {
            int c = ks * 8 + j;
            qa[ks][0] = cvt_tf32(Qg[(size_t)r0 * DK + c] * 0.125f);
            qa[ks][1] = cvt_tf32(Qg[(size_t)(r0 + 8) * DK + c] * 0.125f);
            qa[ks][2] = cvt_tf32(Qg[(size_t)r0 * DK + c + 4] * 0.125f);
            qa[ks][3] = cvt_tf32(Qg[(size_t)(r0 + 8) * DK + c + 4] * 0.125f);
        }
    }

    float o[8][4];
#pragma unroll
    for (int nt = 0; nt < 8; nt++)
#pragma unroll
        for (int e = 0; e < 4; e++) o[nt][e] = 0.f;
    float mrow0 = -1e30f, mrow1 = -1e30f;
    float lrow0 = 0.f, lrow1 = 0.f;

    for (int kc = 0; kc < L_SEQ / 64; kc++) {
        __syncthreads();   // prior chunk's PV reads done before overwrite
        // stage K (into KPs) and V (into Vsm), tf32-converted
#pragma unroll
        for (int it = 0; it < 4; it++) {
            int idx = tid + it * 256;       // 0..1023
            int r   = idx >> 4;             // 0..63
            int c4  = (idx & 15) * 4;       // 0..60
            float4 vk = *(const float4*)(Kg + (size_t)(kc * 64 + r) * DK + c4);
            KPs[r * KS_STRIDE + c4 + 0] = cvt_tf32(vk.x);
            KPs[r * KS_STRIDE + c4 + 1] = cvt_tf32(vk.y);
            KPs[r * KS_STRIDE + c4 + 2] = cvt_tf32(vk.z);
            KPs[r * KS_STRIDE + c4 + 3] = cvt_tf32(vk.w);
            float4 vv = *(const float4*)(Vg + (size_t)(kc * 64 + r) * DK + c4);
            Vsm[r * VS_STRIDE + c4 + 0] = cvt_tf32(vv.x);
            Vsm[r * VS_STRIDE + c4 + 1] = cvt_tf32(vv.y);
            Vsm[r * VS_STRIDE + c4 + 2] = cvt_tf32(vv.z);
            Vsm[r * VS_STRIDE + c4 + 3] = cvt_tf32(vv.w);
        }
        __syncthreads();

        // S = Q K^T  (per warp: 16 x 64)
        float s[8][4];
#pragma unroll
        for (int nt = 0; nt < 8; nt++)
#pragma unroll
            for (int e = 0; e < 4; e++) s[nt][e] = 0.f;
#pragma unroll
        for (int ks = 0; ks < 8; ks++) {
            const int kk = ks * 8;
#pragma unroll
            for (int nt = 0; nt < 8; nt++) {
                uint32_t bf[2] = { KPs[(nt * 8 + g) * KS_STRIDE + kk + j],
                                   KPs[(nt * 8 + g) * KS_STRIDE + kk + j + 4] };
                mma_tf32(s[nt], qa[ks], bf);
            }
        }

        // online softmax (rows g and g+8 of this warp's 16)
        float mx0 = -1e30f, mx1 = -1e30f;
#pragma unroll
        for (int nt = 0; nt < 8; nt++) {
            mx0 = fmaxf(mx0, fmaxf(s[nt][0], s[nt][1]));
            mx1 = fmaxf(mx1, fmaxf(s[nt][2], s[nt][3]));
        }
        mx0 = fmaxf(mx0, __shfl_xor_sync(0xffffffffu, mx0, 1));
        mx0 = fmaxf(mx0, __shfl_xor_sync(0xffffffffu, mx0, 2));
        mx1 = fmaxf(mx1, __shfl_xor_sync(0xffffffffu, mx1, 1));
        mx1 = fmaxf(mx1, __shfl_xor_sync(0xffffffffu, mx1, 2));

        float mn0 = fmaxf(mrow0, mx0), mn1 = fmaxf(mrow1, mx1);
        float al0 = fexp(mrow0 - mn0), al1 = fexp(mrow1 - mn1);
        mrow0 = mn0; mrow1 = mn1;

        float rs0 = 0.f, rs1 = 0.f;
#pragma unroll
        for (int nt = 0; nt < 8; nt++) {
            s[nt][0] = fexp(s[nt][0] - mn0);
            s[nt][1] = fexp(s[nt][1] - mn0);
            s[nt][2] = fexp(s[nt][2] - mn1);
            s[nt][3] = fexp(s[nt][3] - mn1);
            rs0 += s[nt][0] + s[nt][1];
            rs1 += s[nt][2] + s[nt][3];
        }
        rs0 += __shfl_xor_sync(0xffffffffu, rs0, 1);
        rs0 += __shfl_xor_sync(0xffffffffu, rs0, 2);
        rs1 += __shfl_xor_sync(0xffffffffu, rs1, 1);
        rs1 += __shfl_xor_sync(0xffffffffu, rs1, 2);
        lrow0 = lrow0 * al0 + rs0;
        lrow1 = lrow1 * al1 + rs1;

#pragma unroll
        for (int nt = 0; nt < 8; nt++) {
            o[nt][0] *= al0; o[nt][1] *= al0;
            o[nt][2] *= al1; o[nt][3] *= al1;
        }

        __syncthreads();   // all warps done reading K before P overwrites it
        // write P (tf32) into KPs rows [w*16 .. w*16+15]
        {
            int pr0 = (w * 16 + g) * KS_STRIDE;
            int pr1 = (w * 16 + g + 8) * KS_STRIDE;
#pragma unroll
            for (int nt = 0; nt < 8; nt++) {
                int c = nt * 8 + 2 * j;
                uint2 p01 = make_uint2(cvt_tf32(s[nt][0]), cvt_tf32(s[nt][1]));
                *(uint2*)&KPs[pr0 + c] = p01;
                uint2 p23 = make_uint2(cvt_tf32(s[nt][2]), cvt_tf32(s[nt][3]));
                *(uint2*)&KPs[pr1 + c] = p23;
            }
        }
        __syncthreads();

        // O += P V
#pragma unroll
        for (int ks = 0; ks < 8; ks++) {
            const int kk = ks * 8;
            uint32_t pa[4];
            pa[0] = KPs[(w * 16 + g) * KS_STRIDE + kk + j];
            pa[1] = KPs[(w * 16 + g + 8) * KS_STRIDE + kk + j];
            pa[2] = KPs[(w * 16 + g) * KS_STRIDE + kk + j + 4];
            pa[3] = KPs[(w * 16 + g + 8) * KS_STRIDE + kk + j + 4];
#pragma unroll
            for (int nt = 0; nt < 8; nt++) {
                uint32_t bf[2] = { Vsm[(kk + j) * VS_STRIDE + nt * 8 + g],
                                   Vsm[(kk + j + 4) * VS_STRIDE + nt * 8 + g] };
                mma_tf32(o[nt], pa, bf);
            }
        }
    }

    // normalize and write out: out[l][b][h*64 + d]
    float inv0 = 1.0f / lrow0, inv1 = 1.0f / lrow1;
    int r0 = q0 + w * 16 + g;
#pragma unroll
    for (int nt = 0; nt < 8; nt++) {
        int c = nt * 8 + 2 * j;
        float2 v0 = make_float2(o[nt][0] * inv0, o[nt][1] * inv0);
        *(float2*)(out + ((size_t)r0 * BATCH + b) * DM + h * DK + c) = v0;
        float2 v1 = make_float2(o[nt][2] * inv1, o[nt][3] * inv1);
        *(float2*)(out + ((size_t)(r0 + 8) * BATCH + b) * DM + h * DK + c) = v1;
    }
}

// ---------------------------------------------------------------------------
extern "C" void kernel_launch(void* const* d_in, const int* in_sizes, int n_in,
                              void* d_out, int out_size)
{
    const float* X = (const float*)d_in[0];
    const float* W = (const float*)d_in[1];
    float* out = (float*)d_out;

    cudaFuncSetAttribute(flash_kernel,
                         cudaFuncAttributeMaxDynamicSharedMemorySize, FLASH_SMEM);

    qkv_mma_kernel<<<dim3(E3 / 128, MROWS / 128), 256>>>(X, W);
    rope_kernel<<<(HB * L_SEQ * 16) / 256, 256>>>();
    flash_kernel<<<dim3(L_SEQ / 128, HB), 256, FLASH_SMEM>>>(out);
}

// round 4
// speedup vs baseline: 2.9065x; 1.0437x over previous
#include <cuda_runtime.h>
#include <cstdint>
#include <math.h>

#define L_SEQ  2048
#define BATCH  2
#define DM     1024
#define NH     16
#define DK     64
#define E3     3072
#define MROWS  (L_SEQ * BATCH)
#define HB     (NH * BATCH)     // 32

// Scratch (static device allocations — allowed)
__device__ float g_Q[HB * L_SEQ * DK];   // [hb][l][d]
__device__ float g_K[HB * L_SEQ * DK];   // [hb][l][d]
__device__ float g_V[HB * L_SEQ * DK];   // [hb][l][d]

// ---------------------------------------------------------------------------
// helpers
// ---------------------------------------------------------------------------
__device__ __forceinline__ uint32_t cvt_tf32(float x) {
    uint32_t u;
    asm("cvt.rna.tf32.f32 %0, %1;" : "=r"(u) : "f"(x));
    return u;
}

// D += A(16x8) * B(8x8), tf32 inputs, f32 accum
__device__ __forceinline__ void mma_tf32(float* d, const uint32_t* a, const uint32_t* b) {
    asm volatile(
        "mma.sync.aligned.m16n8k8.row.col.f32.tf32.tf32.f32 "
        "{%0,%1,%2,%3}, {%4,%5,%6,%7}, {%8,%9}, {%0,%1,%2,%3};"
        : "+f"(d[0]), "+f"(d[1]), "+f"(d[2]), "+f"(d[3])
        : "r"(a[0]), "r"(a[1]), "r"(a[2]), "r"(a[3]), "r"(b[0]), "r"(b[1]));
}

// fast exp on the FMA pipe; input effectively <= 0
__device__ __forceinline__ float fexp(float x) {
    x = fmaxf(x, -80.0f);
    float t = x * 1.4426950408889634f;
    float n = rintf(t);
    float r = fmaf(n, -0.6931471805599453f, x);
    float p = fmaf(r, 0.00833333333f, 0.04166666667f);
    p = fmaf(p, r, 0.16666666667f);
    p = fmaf(p, r, 0.5f);
    p = fmaf(p, r, 1.0f);
    p = fmaf(p, r, 1.0f);
    return p * __int_as_float(((int)n + 127) << 23);
}

// ---------------------------------------------------------------------------
// Kernel 1: QKV projection (tf32 mma.sync) with FUSED RoPE epilogue.
// C[m,n] = sum_k X[m,k] * W[n,k].  CTA tile 128x128, BK=32, double-buffered
// smem (1 sync per k-step), 8 warps (2x4), warp tile 64x32.
// RoPE pair (d, d+16) for d<16 lives in the SAME thread at (nt, nt+2)
// because d = (wn&1)*32 + nt*8 + 2j + e  (n0 multiple of 64).
// ---------------------------------------------------------------------------
#define QKV_SMEM 73728   // 2 arrays * 2 buffers * 128*36 words * 4B
__global__ __launch_bounds__(256, 2) void qkv_mma_kernel(
    const float* __restrict__ X, const float* __restrict__ W)
{
    extern __shared__ uint32_t sm32[];
    uint32_t* SA = sm32;          // [buf][128][36]
    uint32_t* SB = sm32 + 9216;   // [buf][128][36]

    const int tid  = threadIdx.x;
    const int lane = tid & 31;
    const int w    = tid >> 5;
    const int wm   = w >> 2;       // 0..1
    const int wn   = w & 3;        // 0..3
    const int g    = lane >> 2;    // 0..7
    const int j    = lane & 3;     // 0..3

    const int m0 = blockIdx.y * 128;
    const int n0 = blockIdx.x * 128;

    float acc[4][4][4];
#pragma unroll
    for (int mt = 0; mt < 4; mt++)
#pragma unroll
        for (int nt = 0; nt < 4; nt++)
#pragma unroll
            for (int e = 0; e < 4; e++) acc[mt][nt][e] = 0.f;

    float4 va[4], vb[4];
    // prologue: load + stage k-step 0 into buffer 0
#pragma unroll
    for (int it = 0; it < 4; it++) {
        int idx = tid + it * 256;
        int r   = idx >> 3;
        int c4  = (idx & 7) * 4;
        va[it] = *(const float4*)(X + (size_t)(m0 + r) * DM + c4);
        vb[it] = *(const float4*)(W + (size_t)(n0 + r) * DM + c4);
    }
#pragma unroll
    for (int it = 0; it < 4; it++) {
        int idx = tid + it * 256;
        int r   = idx >> 3;
        int c4  = (idx & 7) * 4;
        uint32_t* pa = SA + r * 36 + c4;
        pa[0] = cvt_tf32(va[it].x); pa[1] = cvt_tf32(va[it].y);
        pa[2] = cvt_tf32(va[it].z); pa[3] = cvt_tf32(va[it].w);
        uint32_t* pb = SB + r * 36 + c4;
        pb[0] = cvt_tf32(vb[it].x); pb[1] = cvt_tf32(vb[it].y);
        pb[2] = cvt_tf32(vb[it].z); pb[3] = cvt_tf32(vb[it].w);
    }
    __syncthreads();

    for (int s = 0; s < 32; s++) {
        if (s < 31) {
            const int k0 = (s + 1) * 32;
#pragma unroll
            for (int it = 0; it < 4; it++) {
                int idx = tid + it * 256;
                int r   = idx >> 3;
                int c4  = (idx & 7) * 4;
                va[it] = *(const float4*)(X + (size_t)(m0 + r) * DM + k0 + c4);
                vb[it] = *(const float4*)(W + (size_t)(n0 + r) * DM + k0 + c4);
            }
        }
        const uint32_t* Ab = SA + (s & 1) * 4608;
        const uint32_t* Bb = SB + (s & 1) * 4608;
#pragma unroll
        for (int ks = 0; ks < 4; ks++) {
            const int kk = ks * 8;
            uint32_t af[4][4];
#pragma unroll
            for (int mt = 0; mt < 4; mt++) {
                int row = wm * 64 + mt * 16 + g;
                af[mt][0] = Ab[row * 36 + kk + j];
                af[mt][1] = Ab[(row + 8) * 36 + kk + j];
                af[mt][2] = Ab[row * 36 + kk + j + 4];
                af[mt][3] = Ab[(row + 8) * 36 + kk + j + 4];
            }
#pragma unroll
            for (int nt = 0; nt < 4; nt++) {
                int col = wn * 32 + nt * 8 + g;
                uint32_t bf[2] = { Bb[col * 36 + kk + j], Bb[col * 36 + kk + j + 4] };
#pragma unroll
                for (int mt = 0; mt < 4; mt++)
                    mma_tf32(acc[mt][nt], af[mt], bf);
            }
        }
        if (s < 31) {
            uint32_t* An = SA + ((s + 1) & 1) * 4608;
            uint32_t* Bn = SB + ((s + 1) & 1) * 4608;
#pragma unroll
            for (int it = 0; it < 4; it++) {
                int idx = tid + it * 256;
                int r   = idx >> 3;
                int c4  = (idx & 7) * 4;
                uint32_t* pa = An + r * 36 + c4;
                pa[0] = cvt_tf32(va[it].x); pa[1] = cvt_tf32(va[it].y);
                pa[2] = cvt_tf32(va[it].z); pa[3] = cvt_tf32(va[it].w);
                uint32_t* pb = Bn + r * 36 + c4;
                pb[0] = cvt_tf32(vb[it].x); pb[1] = cvt_tf32(vb[it].y);
                pb[2] = cvt_tf32(vb[it].z); pb[3] = cvt_tf32(vb[it].w);
            }
            __syncthreads();
        }
    }

    // ---- fused RoPE on accumulators (q and k columns only) ----
    if ((wn & 1) == 0) {
        float thc[2][2], ths_[2][2];   // per (nt, e): theta
#pragma unroll
        for (int nt = 0; nt < 2; nt++)
#pragma unroll
            for (int e = 0; e < 2; e++) {
                int d = nt * 8 + 2 * j + e;
                thc[nt][e] = powf(10000.0f, -(float)d * (1.0f / 16.0f));
                ths_[nt][e] = 0.f;
            }
#pragma unroll
        for (int nt = 0; nt < 2; nt++) {
            int col = n0 + wn * 32 + nt * 8 + 2 * j;
            int h   = col / 192;
            int jj  = col - h * 192;
            int t   = jj >> 6;
            if (t < 2) {   // q or k column
#pragma unroll
                for (int mt = 0; mt < 4; mt++) {
#pragma unroll
                    for (int rr = 0; rr < 2; rr++) {
                        int row = m0 + wm * 64 + mt * 16 + g + rr * 8;
                        float lf = (float)(row >> 1);
#pragma unroll
                        for (int e = 0; e < 2; e++) {
                            float sn, cs;
                            sincosf(lf * thc[nt][e], &sn, &cs);
                            float x1 = acc[mt][nt][rr * 2 + e];
                            float x2 = acc[mt][nt + 2][rr * 2 + e];
                            acc[mt][nt][rr * 2 + e]     = x1 * cs - x2 * sn;
                            acc[mt][nt + 2][rr * 2 + e] = x2 * cs + x1 * sn;
                        }
                    }
                }
            }
        }
        (void)ths_;
    }

    // ---- epilogue scatter ----
#pragma unroll
    for (int mt = 0; mt < 4; mt++) {
#pragma unroll
        for (int nt = 0; nt < 4; nt++) {
            int col = n0 + wn * 32 + nt * 8 + 2 * j;
            int h   = col / 192;
            int jj  = col - h * 192;
            int t   = jj >> 6;
            int d   = jj & 63;
#pragma unroll
            for (int rr = 0; rr < 2; rr++) {
                int row = m0 + wm * 64 + mt * 16 + g + rr * 8;
                int l = row >> 1, b = row & 1;
                int hb = h * 2 + b;
                float2 v = make_float2(acc[mt][nt][rr * 2], acc[mt][nt][rr * 2 + 1]);
                float* dst = (t == 0) ? g_Q : (t == 1) ? g_K : g_V;
                *(float2*)&dst[(((size_t)hb * L_SEQ) + l) * DK + d] = v;
            }
        }
    }
}

// ---------------------------------------------------------------------------
// Kernel 2: fused flash attention, tf32 mma.sync.
// CTA: 128 q rows x one (h,b). 8 warps x 16 q-rows each, 2 CTAs/SM.
// Separate smem regions for K, V, P (P rows are warp-private -> no sync
// between softmax and PV). 2 syncthreads per key chunk. K/V for chunk kc+1
// prefetched into registers before the PV mma of chunk kc.
// ---------------------------------------------------------------------------
#define KS_STRIDE 68
#define VS_STRIDE 72
#define FLASH_SMEM ((64 * KS_STRIDE + 64 * VS_STRIDE + 128 * KS_STRIDE) * 4) // 70656

__global__ __launch_bounds__(256, 2) void flash_kernel(float* __restrict__ out)
{
    extern __shared__ uint32_t fsm[];
    uint32_t* Ks = fsm;                              // [64][68]
    uint32_t* Vs = fsm + 64 * KS_STRIDE;             // [64][72]
    uint32_t* Ps = fsm + 64 * KS_STRIDE + 64 * VS_STRIDE; // [128][68]

    const int tid  = threadIdx.x;
    const int lane = tid & 31;
    const int w    = tid >> 5;     // 0..7
    const int g    = lane >> 2;
    const int j    = lane & 3;

    const int q0 = blockIdx.x * 128;
    const int hb = blockIdx.y;
    const int h  = hb >> 1, b = hb & 1;

    const float* Qg = g_Q + (size_t)hb * L_SEQ * DK;
    const float* Kg = g_K + (size_t)hb * L_SEQ * DK;
    const float* Vg = g_V + (size_t)hb * L_SEQ * DK;

    // Q fragments (x 1/8 scale), kept in registers for all chunks
    uint32_t qa[8][4];
    {
        int r0 = q0 + w * 16 + g;
#pragma unroll
        for (int ks = 0; ks < 8; ks++) {
            int c = ks * 8 + j;
            qa[ks][0] = cvt_tf32(Qg[(size_t)r0 * DK + c] * 0.125f);
            qa[ks][1] = cvt_tf32(Qg[(size_t)(r0 + 8) * DK + c] * 0.125f);
            qa[ks][2] = cvt_tf32(Qg[(size_t)r0 * DK + c + 4] * 0.125f);
            qa[ks][3] = cvt_tf32(Qg[(size_t)(r0 + 8) * DK + c + 4] * 0.125f);
        }
    }

    float o[8][4];
#pragma unroll
    for (int nt = 0; nt < 8; nt++)
#pragma unroll
        for (int e = 0; e < 4; e++) o[nt][e] = 0.f;
    float mrow0 = -1e30f, mrow1 = -1e30f;
    float lrow0 = 0.f, lrow1 = 0.f;

    float4 pk[4], pv[4];
    // prologue: prefetch chunk 0
#pragma unroll
    for (int it = 0; it < 4; it++) {
        int idx = tid + it * 256;
        int r   = idx >> 4;
        int c4  = (idx & 15) * 4;
        pk[it] = *(const float4*)(Kg + (size_t)r * DK + c4);
        pv[it] = *(const float4*)(Vg + (size_t)r * DK + c4);
    }

    for (int kc = 0; kc < L_SEQ / 64; kc++) {
        __syncthreads();   // all warps done with Ks/Vs of previous chunk
#pragma unroll
        for (int it = 0; it < 4; it++) {
            int idx = tid + it * 256;
            int r   = idx >> 4;
            int c4  = (idx & 15) * 4;
            uint32_t* kp = Ks + r * KS_STRIDE + c4;
            kp[0] = cvt_tf32(pk[it].x); kp[1] = cvt_tf32(pk[it].y);
            kp[2] = cvt_tf32(pk[it].z); kp[3] = cvt_tf32(pk[it].w);
            uint32_t* vp = Vs + r * VS_STRIDE + c4;
            vp[0] = cvt_tf32(pv[it].x); vp[1] = cvt_tf32(pv[it].y);
            vp[2] = cvt_tf32(pv[it].z); vp[3] = cvt_tf32(pv[it].w);
        }
        __syncthreads();

        // S = Q K^T  (per warp: 16 x 64)
        float s[8][4];
#pragma unroll
        for (int nt = 0; nt < 8; nt++)
#pragma unroll
            for (int e = 0; e < 4; e++) s[nt][e] = 0.f;
#pragma unroll
        for (int ks = 0; ks < 8; ks++) {
            const int kk = ks * 8;
#pragma unroll
            for (int nt = 0; nt < 8; nt++) {
                uint32_t bf[2] = { Ks[(nt * 8 + g) * KS_STRIDE + kk + j],
                                   Ks[(nt * 8 + g) * KS_STRIDE + kk + j + 4] };
                mma_tf32(s[nt], qa[ks], bf);
            }
        }

        // online softmax (rows g and g+8 of this warp's 16)
        float mx0 = -1e30f, mx1 = -1e30f;
#pragma unroll
        for (int nt = 0; nt < 8; nt++) {
            mx0 = fmaxf(mx0, fmaxf(s[nt][0], s[nt][1]));
            mx1 = fmaxf(mx1, fmaxf(s[nt][2], s[nt][3]));
        }
        mx0 = fmaxf(mx0, __shfl_xor_sync(0xffffffffu, mx0, 1));
        mx0 = fmaxf(mx0, __shfl_xor_sync(0xffffffffu, mx0, 2));
        mx1 = fmaxf(mx1, __shfl_xor_sync(0xffffffffu, mx1, 1));
        mx1 = fmaxf(mx1, __shfl_xor_sync(0xffffffffu, mx1, 2));

        float mn0 = fmaxf(mrow0, mx0), mn1 = fmaxf(mrow1, mx1);
        float al0 = fexp(mrow0 - mn0), al1 = fexp(mrow1 - mn1);
        mrow0 = mn0; mrow1 = mn1;

        float rs0 = 0.f, rs1 = 0.f;
#pragma unroll
        for (int nt = 0; nt < 8; nt++) {
            s[nt][0] = fexp(s[nt][0] - mn0);
            s[nt][1] = fexp(s[nt][1] - mn0);
            s[nt][2] = fexp(s[nt][2] - mn1);
            s[nt][3] = fexp(s[nt][3] - mn1);
            rs0 += s[nt][0] + s[nt][1];
            rs1 += s[nt][2] + s[nt][3];
        }
        rs0 += __shfl_xor_sync(0xffffffffu, rs0, 1);
        rs0 += __shfl_xor_sync(0xffffffffu, rs0, 2);
        rs1 += __shfl_xor_sync(0xffffffffu, rs1, 1);
        rs1 += __shfl_xor_sync(0xffffffffu, rs1, 2);
        lrow0 = lrow0 * al0 + rs0;
        lrow1 = lrow1 * al1 + rs1;

#pragma unroll
        for (int nt = 0; nt < 8; nt++) {
            o[nt][0] *= al0; o[nt][1] *= al0;
            o[nt][2] *= al1; o[nt][3] *= al1;
        }

        // write P (tf32) into this warp's private rows — no sync needed
        {
            int pr0 = (w * 16 + g) * KS_STRIDE;
            int pr1 = (w * 16 + g + 8) * KS_STRIDE;
#pragma unroll
            for (int nt = 0; nt < 8; nt++) {
                int c = nt * 8 + 2 * j;
                uint2 p01 = make_uint2(cvt_tf32(s[nt][0]), cvt_tf32(s[nt][1]));
                *(uint2*)&Ps[pr0 + c] = p01;
                uint2 p23 = make_uint2(cvt_tf32(s[nt][2]), cvt_tf32(s[nt][3]));
                *(uint2*)&Ps[pr1 + c] = p23;
            }
        }

        // prefetch next chunk while PV mma runs
        if (kc + 1 < L_SEQ / 64) {
            const size_t roff = (size_t)(kc + 1) * 64;
#pragma unroll
            for (int it = 0; it < 4; it++) {
                int idx = tid + it * 256;
                int r   = idx >> 4;
                int c4  = (idx & 15) * 4;
                pk[it] = *(const float4*)(Kg + (roff + r) * DK + c4);
                pv[it] = *(const float4*)(Vg + (roff + r) * DK + c4);
            }
        }

        // O += P V
#pragma unroll
        for (int ks = 0; ks < 8; ks++) {
            const int kk = ks * 8;
            uint32_t pa[4];
            pa[0] = Ps[(w * 16 + g) * KS_STRIDE + kk + j];
            pa[1] = Ps[(w * 16 + g + 8) * KS_STRIDE + kk + j];
            pa[2] = Ps[(w * 16 + g) * KS_STRIDE + kk + j + 4];
            pa[3] = Ps[(w * 16 + g + 8) * KS_STRIDE + kk + j + 4];
#pragma unroll
            for (int nt = 0; nt < 8; nt++) {
                uint32_t bf[2] = { Vs[(kk + j) * VS_STRIDE + nt * 8 + g],
                                   Vs[(kk + j + 4) * VS_STRIDE + nt * 8 + g] };
                mma_tf32(o[nt], pa, bf);
            }
        }
    }

    // normalize and write out: out[l][b][h*64 + d]
    float inv0 = 1.0f / lrow0, inv1 = 1.0f / lrow1;
    int r0 = q0 + w * 16 + g;
#pragma unroll
    for (int nt = 0; nt < 8; nt++) {
        int c = nt * 8 + 2 * j;
        float2 v0 = make_float2(o[nt][0] * inv0, o[nt][1] * inv0);
        *(float2*)(out + ((size_t)r0 * BATCH + b) * DM + h * DK + c) = v0;
        float2 v1 = make_float2(o[nt][2] * inv1, o[nt][3] * inv1);
        *(float2*)(out + ((size_t)(r0 + 8) * BATCH + b) * DM + h * DK + c) = v1;
    }
}

// ---------------------------------------------------------------------------
extern "C" void kernel_launch(void* const* d_in, const int* in_sizes, int n_in,
                              void* d_out, int out_size)
{
    const float* X = (const float*)d_in[0];
    const float* W = (const float*)d_in[1];
    float* out = (float*)d_out;

    cudaFuncSetAttribute(qkv_mma_kernel,
                         cudaFuncAttributeMaxDynamicSharedMemorySize, QKV_SMEM);
    cudaFuncSetAttribute(flash_kernel,
                         cudaFuncAttributeMaxDynamicSharedMemorySize, FLASH_SMEM);

    qkv_mma_kernel<<<dim3(E3 / 128, MROWS / 128), 256, QKV_SMEM>>>(X, W);
    flash_kernel<<<dim3(L_SEQ / 128, HB), 256, FLASH_SMEM>>>(out);
}